// round 8
// baseline (speedup 1.0000x reference)
#include <cuda_runtime.h>
#include <cstdint>

#define NN 8192
#define FF 8
#define TPB 128                      // 4 warps
#define GRPW 8                       // rows per warp
#define RPB 32                       // rows per gemv block
#define NGB (NN / RPB)               // 256 gemv blocks
#define NFB 188                      // fid blocks (one-wave: 188+256 = 444 = 148*3)
#define GRID (NFB + NGB)
#define CH 128                       // j per chunk (lane owns 4 consecutive j)
#define NCH (NN / CH)                // 64 chunks
#define XT 1024                      // x tile nodes (8 chunks)
#define FTS 128                      // fid tile
#define FT (NN / FTS)                // 64
#define NPAIRS (FT * (FT + 1) / 2)   // 2080 tile pairs
#define RT9 0.94868329805051381f     // sqrt(0.9)
#define SMEM_DYN 32768

typedef unsigned long long ull;

__device__ float g_dense[NN * FF];

// ---------------- f32x2 helpers ----------------
__device__ __forceinline__ ull fma2(ull a, ull b, ull c) {
    ull d; asm("fma.rn.f32x2 %0, %1, %2, %3;" : "=l"(d) : "l"(a), "l"(b), "l"(c)); return d;
}
__device__ __forceinline__ ull mul2(ull a, ull b) {
    ull d; asm("mul.rn.f32x2 %0, %1, %2;" : "=l"(d) : "l"(a), "l"(b)); return d;
}
__device__ __forceinline__ ull add2(ull a, ull b) {
    ull d; asm("add.rn.f32x2 %0, %1, %2;" : "=l"(d) : "l"(a), "l"(b)); return d;
}
__device__ __forceinline__ ull pack2(float lo, float hi) {
    ull d; asm("mov.b64 %0, {%1, %2};" : "=l"(d) : "f"(lo), "f"(hi)); return d;
}
__device__ __forceinline__ void unpack2(ull v, float& lo, float& hi) {
    asm("mov.b64 {%0, %1}, %2;" : "=f"(lo), "=f"(hi) : "l"(v));
}
__device__ __forceinline__ float ftanh(float x) {
    float t = fabsf(x);
    float e = __expf(-2.0f * t);
    float r = __fdividef(1.0f - e, 1.0f + e);
    return copysignf(r, x);
}
__device__ __forceinline__ float fsigmoid(float x) {
    float e = __expf(-fabsf(x));
    float p = __fdividef(1.0f, 1.0f + e);
    return (x >= 0.0f) ? p : 1.0f - p;
}

// =================================================================
// Mixed kernel, single wave of 444 blocks:
//   blocks [0, 188): fid blocks, grid-striding over 2080 tile-pairs
//   blocks [188, 444): dense gemv (A @ X)
// Both atomicAdd into g_dense (zeroed before launch). fid is
// issue-bound and hides inside gemv's DRAM stalls on the same SMs.
// =================================================================
__global__ void __launch_bounds__(TPB, 3)
mixed_kernel(const float* __restrict__ A, const float* __restrict__ X)
{
    extern __shared__ __align__(16) char sm[];
    const int tid  = threadIdx.x;
    const int lane = tid & 31;
    const int warp = tid >> 5;

    uint32_t smb;
    asm("{ .reg .u64 t; cvta.to.shared.u64 t, %1; cvt.u32.u64 %0, t; }"
        : "=r"(smb) : "l"(sm));

    if (blockIdx.x >= NFB) {
        // ===================== gemv =====================
        // smem x layout (position-permuted): node j in tile:
        // c=j>>7 (chunk), l=(j>>2)&31 (lane), r=j&3; feature pairs at
        // c*4096 + (2r+{0,1})*512 + l*16 (f4-7 at +64B within plane)
        const int i0 = (blockIdx.x - NFB) * RPB + warp * GRPW;

        ull acc[GRPW][4];
        #pragma unroll
        for (int r = 0; r < GRPW; r++)
            #pragma unroll
            for (int kk = 0; kk < 4; kk++) acc[r][kk] = 0ull;

        const float* Ab = A + (size_t)i0 * NN + lane * 4;
        float4 b0[GRPW], b1[GRPW];

        #define LDA(n, B)                                                      \
            do {                                                               \
                int n_ = (n); if (n_ >= NCH) n_ -= NCH;                        \
                const float* p_ = Ab + (size_t)n_ * CH;                        \
                _Pragma("unroll")                                              \
                for (int r_ = 0; r_ < GRPW; r_++)                              \
                    (B)[r_] = __ldcs(reinterpret_cast<const float4*>(p_ + (size_t)r_ * NN)); \
            } while (0)

        #define HALF(B, c0, c1, q0off)                                         \
            do {                                                                \
                ull pa0_, pa1_, pb0_, pb1_, pc0_, pc1_, pd0_, pd1_;             \
                asm("ld.shared.v2.b64 {%0, %1}, [%2];" : "=l"(pa0_), "=l"(pa1_) \
                    : "r"(ba_ + (q0off)));                                      \
                asm("ld.shared.v2.b64 {%0, %1}, [%2];" : "=l"(pb0_), "=l"(pb1_) \
                    : "r"(ba_ + (q0off) + 512));                                \
                asm("ld.shared.v2.b64 {%0, %1}, [%2];" : "=l"(pc0_), "=l"(pc1_) \
                    : "r"(ba_ + (q0off) + 1024));                               \
                asm("ld.shared.v2.b64 {%0, %1}, [%2];" : "=l"(pd0_), "=l"(pd1_) \
                    : "r"(ba_ + (q0off) + 1536));                               \
                _Pragma("unroll")                                               \
                for (int r_ = 0; r_ < GRPW; r_++) {                             \
                    ull w0_ = pack2((B)[r_].c0, (B)[r_].c0);                    \
                    acc[r_][0] = fma2(w0_, pa0_, acc[r_][0]);                   \
                    acc[r_][1] = fma2(w0_, pa1_, acc[r_][1]);                   \
                    acc[r_][2] = fma2(w0_, pb0_, acc[r_][2]);                   \
                    acc[r_][3] = fma2(w0_, pb1_, acc[r_][3]);                   \
                    ull w1_ = pack2((B)[r_].c1, (B)[r_].c1);                    \
                    acc[r_][0] = fma2(w1_, pc0_, acc[r_][0]);                   \
                    acc[r_][1] = fma2(w1_, pc1_, acc[r_][1]);                   \
                    acc[r_][2] = fma2(w1_, pd0_, acc[r_][2]);                   \
                    acc[r_][3] = fma2(w1_, pd1_, acc[r_][3]);                   \
                }                                                               \
            } while (0)

        #define COMPUTE(cl, B)                                                  \
            do {                                                                \
                const uint32_t ba_ = smb + (uint32_t)(cl) * 4096 + (uint32_t)lane * 16; \
                HALF(B, x, y, 0);                                               \
                HALF(B, z, w, 2048);                                            \
            } while (0)

        LDA(0, b0); LDA(1, b1);

        #pragma unroll 1
        for (int t = 0; t < NCH / 8; t++) {
            __syncthreads();     // previous tile fully consumed
            const int t0 = t * XT;
            for (int j = tid; j < XT; j += TPB) {
                const float4* xp = reinterpret_cast<const float4*>(X + (size_t)(t0 + j) * FF);
                float4 a = __ldg(xp), b = __ldg(xp + 1);
                const int cc = j >> 7, ll = (j >> 2) & 31, rr = j & 3;
                ull* dst = reinterpret_cast<ull*>(sm + cc * 4096 + (2 * rr) * 512 + ll * 16);
                dst[0]  = pack2(a.x, a.y);
                dst[1]  = pack2(a.z, a.w);
                dst[64] = pack2(b.x, b.y);
                dst[65] = pack2(b.z, b.w);
            }
            __syncthreads();

            #pragma unroll 1
            for (int cc = 0; cc < 8; cc += 2) {
                const int n = t * 8 + cc;
                COMPUTE(cc,     b0); LDA(n + 2, b0);
                COMPUTE(cc + 1, b1); LDA(n + 3, b1);
            }
        }
        #undef LDA
        #undef HALF
        #undef COMPUTE

        // warp butterfly reduction
        #pragma unroll
        for (int r = 0; r < GRPW; r++)
            #pragma unroll
            for (int kk = 0; kk < 4; kk++) {
                ull v = acc[r][kk];
                #pragma unroll
                for (int o = 16; o; o >>= 1)
                    v = add2(v, __shfl_xor_sync(0xffffffffu, v, o));
                acc[r][kk] = v;
            }

        if (lane < GRPW) {
            const int row = i0 + lane;
            #pragma unroll
            for (int kk = 0; kk < 4; kk++) {
                float lo, hi;
                unpack2(acc[lane][kk], lo, hi);
                atomicAdd(&g_dense[(size_t)row * FF + 2 * kk],     lo);
                atomicAdd(&g_dense[(size_t)row * FF + 2 * kk + 1], hi);
            }
        }
    } else {
        // ===================== fid =====================
        // grid-stride over tile-pairs; fid ⟺ |xn_i·xn_j| >= sqrt(0.9);
        // hit makes the effective weight exactly 1: add (1-A)*x.
        ull* pb = reinterpret_cast<ull*>(sm);
        const uint32_t pbb = smb;
        const int t = tid;

        #pragma unroll 1
        for (int p = blockIdx.x; p < NPAIRS; p += NFB) {
            int ti = 0, rem = p;
            while (rem >= FT - ti) { rem -= FT - ti; ti++; }
            const int tj = ti + rem;

            __syncthreads();   // previous pair's pb reads done

            // own i-row normalized (registers)
            ull xi0, xi1, xi2, xi3;
            {
                const float4* xp = reinterpret_cast<const float4*>(X + (size_t)(ti * FTS + t) * FF);
                float4 a = __ldg(xp), c = __ldg(xp + 1);
                float ss = a.x*a.x + a.y*a.y + a.z*a.z + a.w*a.w
                         + c.x*c.x + c.y*c.y + c.z*c.z + c.w*c.w;
                float inv = 1.0f / (sqrtf(ss) + 1e-12f);
                xi0 = pack2(a.x*inv, a.y*inv);
                xi1 = pack2(a.z*inv, a.w*inv);
                xi2 = pack2(c.x*inv, c.y*inv);
                xi3 = pack2(c.z*inv, c.w*inv);
            }
            // j-tile normalized into smem (32B per node)
            {
                const float4* xp = reinterpret_cast<const float4*>(X + (size_t)(tj * FTS + t) * FF);
                float4 a = __ldg(xp), c = __ldg(xp + 1);
                float ss = a.x*a.x + a.y*a.y + a.z*a.z + a.w*a.w
                         + c.x*c.x + c.y*c.y + c.z*c.z + c.w*c.w;
                float inv = 1.0f / (sqrtf(ss) + 1e-12f);
                pb[t*4 + 0] = pack2(a.x*inv, a.y*inv);
                pb[t*4 + 1] = pack2(a.z*inv, a.w*inv);
                pb[t*4 + 2] = pack2(c.x*inv, c.y*inv);
                pb[t*4 + 3] = pack2(c.z*inv, c.w*inv);
            }
            __syncthreads();

            const int jstart = (ti == tj) ? (t + 1) : 0;

            #pragma unroll 4
            for (int j = jstart; j < FTS; j++) {
                ull q0, q1, q2, q3;
                asm("ld.shared.v2.b64 {%0, %1}, [%2];" : "=l"(q0), "=l"(q1)
                    : "r"(pbb + (uint32_t)j * 32));
                asm("ld.shared.v2.b64 {%0, %1}, [%2];" : "=l"(q2), "=l"(q3)
                    : "r"(pbb + (uint32_t)j * 32 + 16));
                ull d = mul2(xi0, q0);
                d = fma2(xi1, q1, d);
                d = fma2(xi2, q2, d);
                d = fma2(xi3, q3, d);
                float lo, hi; unpack2(d, lo, hi);
                const float s = lo + hi;
                if (fabsf(s) >= RT9) {           // rare (~1e-4)
                    const int gi = ti * FTS + t;
                    const int gj = tj * FTS + j;
                    const float aij = __ldg(A + (size_t)gi * NN + gj);
                    const float aji = __ldg(A + (size_t)gj * NN + gi);
                    const float* xjv = X + (size_t)gj * FF;
                    const float* xiv = X + (size_t)gi * FF;
                    #pragma unroll
                    for (int f = 0; f < FF; f++)
                        atomicAdd(&g_dense[(size_t)gi * FF + f], (1.0f - aij) * __ldg(xjv + f));
                    #pragma unroll
                    for (int f = 0; f < FF; f++)
                        atomicAdd(&g_dense[(size_t)gj * FF + f], (1.0f - aji) * __ldg(xiv + f));
                }
            }
        }
    }
}

// =================================================================
// MLP tail (weights staged in smem), 64 blocks x 128 threads
// =================================================================
#define NW_TOT 785
__global__ void __launch_bounds__(128)
mlp_kernel(const float* __restrict__ Wfm, const float* __restrict__ bfm,
           const float* __restrict__ Wc1, const float* __restrict__ bc1,
           const float* __restrict__ Wp1, const float* __restrict__ bp1,
           const float* __restrict__ Wc2, const float* __restrict__ bc2,
           const float* __restrict__ Wp2, const float* __restrict__ bp2,
           const float* __restrict__ Wc3, const float* __restrict__ bc3,
           const float* __restrict__ Wh,  const float* __restrict__ bh,
           float* __restrict__ out)
{
    __shared__ float w[NW_TOT];
    const int tid = threadIdx.x;

    struct Seg { const float* src; int off, n; };
    const Seg segs[14] = {
        {Wfm,   0, 128}, {bfm, 128, 16}, {Wc1, 144, 256}, {bc1, 400, 16},
        {Wp1, 416, 192}, {bp1, 608, 12}, {Wc2, 620,  96}, {bc2, 716,  8},
        {Wp2, 724,  32}, {bp2, 756,  4}, {Wc3, 760,  16}, {bc3, 776,  4},
        {Wh,  780,   4}, {bh,  784,  1}
    };
    #pragma unroll
    for (int s = 0; s < 14; s++)
        for (int k = tid; k < segs[s].n; k += 128)
            w[segs[s].off + k] = __ldg(segs[s].src + k);
    __syncthreads();

    const int i = blockIdx.x * 128 + tid;

    float v[16], h[16];
    #pragma unroll
    for (int k = 0; k < 8; k++) v[k] = g_dense[(size_t)i * FF + k];

    #define LAYER(IN, OUT, WOFF, BOFF, src, dst)                          \
        do {                                                              \
            _Pragma("unroll")                                             \
            for (int j_ = 0; j_ < (OUT); j_++) {                          \
                float s_ = w[(BOFF) + j_];                                \
                _Pragma("unroll")                                         \
                for (int k_ = 0; k_ < (IN); k_++)                         \
                    s_ = fmaf((src)[k_], w[(WOFF) + k_ * (OUT) + j_], s_);\
                (dst)[j_] = ftanh(s_);                                    \
            }                                                             \
        } while (0)

    LAYER(8, 16,   0, 128, v, h);
    LAYER(16, 16, 144, 400, h, v);
    LAYER(16, 12, 416, 608, v, h);
    LAYER(12, 8,  620, 716, h, v);
    LAYER(8, 4,   724, 756, v, h);
    LAYER(4, 4,   760, 776, h, v);
    #undef LAYER

    float z = w[784];
    #pragma unroll
    for (int k = 0; k < 4; k++)
        z = fmaf(v[k], w[780 + k], z);
    out[i] = fsigmoid(z);
}

extern "C" void kernel_launch(void* const* d_in, const int* in_sizes, int n_in,
                              void* d_out, int out_size)
{
    const float* A = (const float*)d_in[0];
    const float* X = (const float*)d_in[1];

    void* gd = nullptr;
    cudaGetSymbolAddress(&gd, g_dense);
    cudaMemsetAsync(gd, 0, sizeof(float) * NN * FF, 0);

    mixed_kernel<<<GRID, TPB, SMEM_DYN>>>(A, X);

    mlp_kernel<<<NN / 128, 128>>>(
        (const float*)d_in[2],  (const float*)d_in[3],
        (const float*)d_in[4],  (const float*)d_in[5],
        (const float*)d_in[6],  (const float*)d_in[7],
        (const float*)d_in[8],  (const float*)d_in[9],
        (const float*)d_in[10], (const float*)d_in[11],
        (const float*)d_in[12], (const float*)d_in[13],
        (const float*)d_in[14], (const float*)d_in[15],
        (float*)d_out);
}